// round 7
// baseline (speedup 1.0000x reference)
#include <cuda_runtime.h>
#include <cmath>

#define NLV 16
#define TABLE_SIZE (1u << 19)
#define HMASK (TABLE_SIZE - 1u)
#define P1 2654435761u
#define P2 805459861u

#define NP_MAX 1000000
#define GRID_BITS 6
#define GRID_RES (1 << GRID_BITS)          // 64
#define NBINS (1 << (3 * GRID_BITS))       // 262144
#define SCAN_BLOCK 512
#define NSCAN_BLOCKS (NBINS / SCAN_BLOCK)  // 512
#define BRICK_MAX 64

struct ResParams { int r[NLV]; };

// ---- scratch (static device globals; no allocation) ----
__device__ unsigned g_hist[NBINS];
__device__ unsigned long long g_desc[NSCAN_BLOCKS];  // (flag<<32)|value
__device__ float4   g_pts[NP_MAX];   // x,y,z, perm-as-bits

// ---------------- Morton ----------------
__device__ __forceinline__ unsigned expand_bits(unsigned v) {
    v &= 0x3FFu;
    v = (v | (v << 16)) & 0x030000FFu;
    v = (v | (v << 8))  & 0x0300F00Fu;
    v = (v | (v << 4))  & 0x030C30C3u;
    v = (v | (v << 2))  & 0x09249249u;
    return v;
}
__device__ __forceinline__ unsigned morton3(float x, float y, float z) {
    unsigned ix = min((unsigned)(x * (float)GRID_RES), (unsigned)(GRID_RES - 1));
    unsigned iy = min((unsigned)(y * (float)GRID_RES), (unsigned)(GRID_RES - 1));
    unsigned iz = min((unsigned)(z * (float)GRID_RES), (unsigned)(GRID_RES - 1));
    return (expand_bits(ix) << 2) | (expand_bits(iy) << 1) | expand_bits(iz);
}

// ---------------- hist (4 points / thread, vectorized loads) ----------------
__global__ void k_hist(const float* __restrict__ coords, int n) {
    int i = blockIdx.x * blockDim.x + threadIdx.x;   // group of 4 points
    int p0 = i * 4;
    if (p0 + 3 < n) {
        const float4* c4 = (const float4*)coords;
        float4 a = __ldg(&c4[i * 3 + 0]);
        float4 b = __ldg(&c4[i * 3 + 1]);
        float4 c = __ldg(&c4[i * 3 + 2]);
        atomicAdd(&g_hist[morton3(a.x, a.y, a.z)], 1u);
        atomicAdd(&g_hist[morton3(a.w, b.x, b.y)], 1u);
        atomicAdd(&g_hist[morton3(b.z, b.w, c.x)], 1u);
        atomicAdd(&g_hist[morton3(c.y, c.z, c.w)], 1u);
    } else {
        for (int p = p0; p < n; ++p) {
            atomicAdd(&g_hist[morton3(coords[3*p], coords[3*p+1], coords[3*p+2])], 1u);
        }
    }
}

// ---------------- single-pass scan (decoupled lookback) ----------------
__device__ __forceinline__ unsigned warp_incl_scan(unsigned v, int lane) {
    #pragma unroll
    for (int o = 1; o < 32; o <<= 1) {
        unsigned u = __shfl_up_sync(0xFFFFFFFFu, v, o);
        if (lane >= o) v += u;
    }
    return v;
}

__global__ __launch_bounds__(SCAN_BLOCK)
void k_scan_lookback() {
    __shared__ unsigned warp_sums[16];
    __shared__ unsigned s_prefix;
    int b = blockIdx.x, t = threadIdx.x;
    int lane = t & 31, w = t >> 5;

    unsigned v = g_hist[b * SCAN_BLOCK + t];
    unsigned inc = warp_incl_scan(v, lane);
    if (lane == 31) warp_sums[w] = inc;
    __syncthreads();
    if (w == 0) {
        unsigned ws = (lane < 16) ? warp_sums[lane] : 0u;
        ws = warp_incl_scan(ws, lane);
        if (lane < 16) warp_sums[lane] = ws;
    }
    __syncthreads();
    unsigned warp_off = (w > 0) ? warp_sums[w - 1] : 0u;
    unsigned blocksum = warp_sums[15];

    if (w == 0) {
        if (lane == 0) {
            unsigned long long d = ((unsigned long long)((b == 0) ? 2u : 1u) << 32)
                                   | (unsigned long long)blocksum;
            atomicExch(&g_desc[b], d);
            if (b == 0) s_prefix = 0u;
        }
        if (b > 0) {
            unsigned ex = 0;
            int base = b - 1;
            while (true) {
                int j = base - lane;
                unsigned long long d;
                unsigned flag;
                do {
                    d = (j >= 0) ? atomicAdd(&g_desc[j], 0ull)
                                 : ((unsigned long long)2u << 32);
                    flag = (unsigned)(d >> 32);
                } while (__any_sync(0xFFFFFFFFu, flag == 0u));
                unsigned contrib = (unsigned)d;
                unsigned ballot = __ballot_sync(0xFFFFFFFFu, flag == 2u);
                if (ballot) {
                    int L = __ffs(ballot) - 1;
                    if (lane > L) contrib = 0u;
                    ex += __reduce_add_sync(0xFFFFFFFFu, contrib);
                    break;
                } else {
                    ex += __reduce_add_sync(0xFFFFFFFFu, contrib);
                    base -= 32;
                }
            }
            if (lane == 0) {
                atomicExch(&g_desc[b],
                    ((unsigned long long)2u << 32) | (unsigned long long)(ex + blocksum));
                s_prefix = ex;
            }
        }
    }
    __syncthreads();
    g_hist[b * SCAN_BLOCK + t] = s_prefix + warp_off + inc - v;  // exclusive
}

// ---------------- scatter (4 points / thread) ----------------
__device__ __forceinline__ void scatter_one(float x, float y, float z, int idx) {
    unsigned key = morton3(x, y, z);
    unsigned pos = atomicAdd(&g_hist[key], 1u);
    g_pts[pos] = make_float4(x, y, z, __int_as_float(idx));
}

__global__ void k_scatter(const float* __restrict__ coords, int n) {
    int i = blockIdx.x * blockDim.x + threadIdx.x;
    int p0 = i * 4;
    if (p0 + 3 < n) {
        const float4* c4 = (const float4*)coords;
        float4 a = __ldg(&c4[i * 3 + 0]);
        float4 b = __ldg(&c4[i * 3 + 1]);
        float4 c = __ldg(&c4[i * 3 + 2]);
        scatter_one(a.x, a.y, a.z, p0 + 0);
        scatter_one(a.w, b.x, b.y, p0 + 1);
        scatter_one(b.z, b.w, c.x, p0 + 2);
        scatter_one(c.y, c.z, c.w, p0 + 3);
    } else {
        for (int p = p0; p < n; ++p)
            scatter_one(coords[3*p], coords[3*p+1], coords[3*p+2], p);
    }
}

// ---------------- warp reductions ----------------
__device__ __forceinline__ int wmin(int v) {
    #pragma unroll
    for (int o = 16; o; o >>= 1) v = min(v, __shfl_xor_sync(0xFFFFFFFFu, v, o));
    return v;
}
__device__ __forceinline__ int wmax(int v) {
    #pragma unroll
    for (int o = 16; o; o >>= 1) v = max(v, __shfl_xor_sync(0xFFFFFFFFu, v, o));
    return v;
}

// ---------------- main kernel ----------------
// block = 512 threads = 16 warps; warp w handles level w for 32 sorted points.
__global__ __launch_bounds__(512)
void hashgrid_main(const float* __restrict__ tables,
                   float* __restrict__ out,
                   ResParams rp, int n_points)
{
    __shared__ float  s_pt[32 * 4];        // x,y,z,permbits per point
    __shared__ float  s_out[32][33];
    __shared__ float2 s_brick[16][BRICK_MAX];

    int t = threadIdx.x;
    int w = t >> 5;          // level
    int lane = t & 31;       // point within tile
    int base = blockIdx.x * 32;

    // cooperative coalesced load of 32 float4 (512B)
    if (t < 128) {
        int idx = base * 4 + t;
        s_pt[t] = (idx < n_points * 4) ? ((const float*)g_pts)[idx] : 0.0f;
    }
    __syncthreads();

    // All lanes compute (invalid lanes use zero coords; stores guarded below).
    float cx = s_pt[lane * 4 + 0];
    float cy = s_pt[lane * 4 + 1];
    float cz = s_pt[lane * 4 + 2];

    int ires = rp.r[w];
    float res = (float)ires;

    float sx = cx * res, sy = cy * res, sz = cz * res;
    float fx = floorf(sx), fy = floorf(sy), fz = floorf(sz);
    float wx = sx - fx, wy = sy - fy, wz = sz - fz;

    int ifx = (int)fx, ify = (int)fy, ifz = (int)fz;

    const float2* __restrict__ tbl =
        (const float2*)tables + (size_t)w * TABLE_SIZE;

    float2 f000, f001, f010, f011, f100, f101, f110, f111;

    // warp-uniform bounding brick of corner lattice
    int mnx = wmin(ifx), mxx = wmax(ifx);
    int mny = wmin(ify), mxy = wmax(ify);
    int mnz = wmin(ifz), mxz = wmax(ifz);
    int bx = mxx - mnx + 2, by = mxy - mny + 2, bz = mxz - mnz + 2;
    int nc = bx * by * bz;

    if (nc <= BRICK_MAX) {
        // cooperative gather of distinct corners (<=2 rounds)
        float2* sb = s_brick[w];
        int byz = by * bz;
        for (int c = lane; c < nc; c += 32) {
            int i = c / byz;
            int rem = c - i * byz;
            int j = rem / bz;
            int k = rem - j * bz;
            unsigned h = ((unsigned)((mnx + i) * ires)
                        + (unsigned)((mny + j) * ires) * P1
                        + (unsigned)((mnz + k) * ires) * P2) & HMASK;
            sb[c] = __ldg(tbl + h);
        }
        __syncwarp();
        int b000 = (ifx - mnx) * byz + (ify - mny) * bz + (ifz - mnz);
        f000 = sb[b000];
        f001 = sb[b000 + 1];
        f010 = sb[b000 + bz];
        f011 = sb[b000 + bz + 1];
        f100 = sb[b000 + byz];
        f101 = sb[b000 + byz + 1];
        f110 = sb[b000 + byz + bz];
        f111 = sb[b000 + byz + bz + 1];
    } else {
        // per-lane gathers (fine levels): 8 independent LDG.64
        unsigned ux = (unsigned)(ifx * ires);
        unsigned uy = (unsigned)(ify * ires) * P1;
        unsigned uz = (unsigned)(ifz * ires) * P2;
        unsigned dx = (unsigned)ires;
        unsigned dy = (unsigned)ires * P1;
        unsigned dz = (unsigned)ires * P2;

        f000 = __ldg(tbl + ((ux      + uy      + uz     ) & HMASK));
        f001 = __ldg(tbl + ((ux      + uy      + uz + dz) & HMASK));
        f010 = __ldg(tbl + ((ux      + uy + dy + uz     ) & HMASK));
        f011 = __ldg(tbl + ((ux      + uy + dy + uz + dz) & HMASK));
        f100 = __ldg(tbl + ((ux + dx + uy      + uz     ) & HMASK));
        f101 = __ldg(tbl + ((ux + dx + uy      + uz + dz) & HMASK));
        f110 = __ldg(tbl + ((ux + dx + uy + dy + uz     ) & HMASK));
        f111 = __ldg(tbl + ((ux + dx + uy + dy + uz + dz) & HMASK));
    }

    float ex = 1.0f - wx, ey = 1.0f - wy, ez = 1.0f - wz;

    float c00a = f000.x * ex + f100.x * wx;
    float c00b = f000.y * ex + f100.y * wx;
    float c01a = f001.x * ex + f101.x * wx;
    float c01b = f001.y * ex + f101.y * wx;
    float c10a = f010.x * ex + f110.x * wx;
    float c10b = f010.y * ex + f110.y * wx;
    float c11a = f011.x * ex + f111.x * wx;
    float c11b = f011.y * ex + f111.y * wx;

    float c0a = c00a * ey + c10a * wy;
    float c0b = c00b * ey + c10b * wy;
    float c1a = c01a * ey + c11a * wy;
    float c1b = c01b * ey + c11b * wy;

    s_out[lane][2 * w]     = c0a * ez + c1a * wz;
    s_out[lane][2 * w + 1] = c0b * ez + c1b * wz;
    __syncthreads();

    // coalesced writeout: warp w writes rows w and w+16 (128B contiguous each)
    #pragma unroll
    for (int it = 0; it < 2; ++it) {
        int row = w + 16 * it;
        if (base + row < n_points) {
            int gp = __float_as_int(s_pt[row * 4 + 3]);
            out[(size_t)gp * 32 + lane] = s_out[row][lane];
        }
    }
}

// ---------------- launch ----------------
extern "C" void kernel_launch(void* const* d_in, const int* in_sizes, int n_in,
                              void* d_out, int out_size)
{
    const float* coords = (const float*)d_in[0];
    const float* tables = (const float*)d_in[1];
    float* out = (float*)d_out;
    int n_points = in_sizes[0] / 3;

    ResParams rp;
    double g = std::log(512.0 / 16.0) / 15.0;
    for (int l = 0; l < NLV; ++l)
        rp.r[l] = (int)std::floor(16.0 * std::exp((double)l * g));

    void* hist_ptr = nullptr;
    cudaGetSymbolAddress(&hist_ptr, g_hist);
    cudaMemsetAsync(hist_ptr, 0, NBINS * sizeof(unsigned));
    void* desc_ptr = nullptr;
    cudaGetSymbolAddress(&desc_ptr, g_desc);
    cudaMemsetAsync(desc_ptr, 0, NSCAN_BLOCKS * sizeof(unsigned long long));

    int b = 256;
    int ngroups = (n_points + 4 * b - 1) / (4 * b);
    k_hist<<<ngroups, b>>>(coords, n_points);
    k_scan_lookback<<<NSCAN_BLOCKS, SCAN_BLOCK>>>();
    k_scatter<<<ngroups, b>>>(coords, n_points);

    int ntiles = (n_points + 31) / 32;
    hashgrid_main<<<ntiles, 512>>>(tables, out, rp, n_points);
}

// round 8
// speedup vs baseline: 1.3089x; 1.3089x over previous
#include <cuda_runtime.h>
#include <cmath>

#define NLV 16
#define TABLE_SIZE (1u << 19)
#define HMASK (TABLE_SIZE - 1u)
#define P1 2654435761u
#define P2 805459861u

#define NP_MAX 1000000
#define GRID_BITS 6
#define GRID_RES (1 << GRID_BITS)          // 64
#define NBINS (1 << (3 * GRID_BITS))       // 262144
#define SCAN_BLOCK 512
#define NSCAN_BLOCKS (NBINS / SCAN_BLOCK)  // 512

struct ResParams { int r[NLV]; };

// ---- scratch (static device globals; no allocation) ----
__device__ unsigned g_hist[NBINS];
__device__ unsigned long long g_desc[NSCAN_BLOCKS];  // (flag<<32)|value
__device__ float4   g_pts[NP_MAX];   // x,y,z, perm-as-bits

// ---------------- Morton ----------------
__device__ __forceinline__ unsigned expand_bits(unsigned v) {
    v &= 0x3FFu;
    v = (v | (v << 16)) & 0x030000FFu;
    v = (v | (v << 8))  & 0x0300F00Fu;
    v = (v | (v << 4))  & 0x030C30C3u;
    v = (v | (v << 2))  & 0x09249249u;
    return v;
}
__device__ __forceinline__ unsigned morton3(float x, float y, float z) {
    unsigned ix = min((unsigned)(x * (float)GRID_RES), (unsigned)(GRID_RES - 1));
    unsigned iy = min((unsigned)(y * (float)GRID_RES), (unsigned)(GRID_RES - 1));
    unsigned iz = min((unsigned)(z * (float)GRID_RES), (unsigned)(GRID_RES - 1));
    return (expand_bits(ix) << 2) | (expand_bits(iy) << 1) | expand_bits(iz);
}

// ---------------- hist (4 points / thread, vectorized loads) ----------------
__global__ void k_hist(const float* __restrict__ coords, int n) {
    int i = blockIdx.x * blockDim.x + threadIdx.x;   // group of 4 points
    int p0 = i * 4;
    if (p0 + 3 < n) {
        const float4* c4 = (const float4*)coords;
        float4 a = __ldg(&c4[i * 3 + 0]);
        float4 b = __ldg(&c4[i * 3 + 1]);
        float4 c = __ldg(&c4[i * 3 + 2]);
        atomicAdd(&g_hist[morton3(a.x, a.y, a.z)], 1u);
        atomicAdd(&g_hist[morton3(a.w, b.x, b.y)], 1u);
        atomicAdd(&g_hist[morton3(b.z, b.w, c.x)], 1u);
        atomicAdd(&g_hist[morton3(c.y, c.z, c.w)], 1u);
    } else {
        for (int p = p0; p < n; ++p) {
            atomicAdd(&g_hist[morton3(coords[3*p], coords[3*p+1], coords[3*p+2])], 1u);
        }
    }
}

// ---------------- single-pass scan (decoupled lookback) ----------------
__device__ __forceinline__ unsigned warp_incl_scan(unsigned v, int lane) {
    #pragma unroll
    for (int o = 1; o < 32; o <<= 1) {
        unsigned u = __shfl_up_sync(0xFFFFFFFFu, v, o);
        if (lane >= o) v += u;
    }
    return v;
}

__global__ __launch_bounds__(SCAN_BLOCK)
void k_scan_lookback() {
    __shared__ unsigned warp_sums[16];
    __shared__ unsigned s_prefix;
    int b = blockIdx.x, t = threadIdx.x;
    int lane = t & 31, w = t >> 5;

    unsigned v = g_hist[b * SCAN_BLOCK + t];
    unsigned inc = warp_incl_scan(v, lane);
    if (lane == 31) warp_sums[w] = inc;
    __syncthreads();
    if (w == 0) {
        unsigned ws = (lane < 16) ? warp_sums[lane] : 0u;
        ws = warp_incl_scan(ws, lane);
        if (lane < 16) warp_sums[lane] = ws;
    }
    __syncthreads();
    unsigned warp_off = (w > 0) ? warp_sums[w - 1] : 0u;
    unsigned blocksum = warp_sums[15];

    if (w == 0) {
        if (lane == 0) {
            unsigned long long d = ((unsigned long long)((b == 0) ? 2u : 1u) << 32)
                                   | (unsigned long long)blocksum;
            atomicExch(&g_desc[b], d);
            if (b == 0) s_prefix = 0u;
        }
        if (b > 0) {
            unsigned ex = 0;
            int base = b - 1;
            while (true) {
                int j = base - lane;
                unsigned long long d;
                unsigned flag;
                do {
                    d = (j >= 0) ? atomicAdd(&g_desc[j], 0ull)
                                 : ((unsigned long long)2u << 32);
                    flag = (unsigned)(d >> 32);
                } while (__any_sync(0xFFFFFFFFu, flag == 0u));
                unsigned contrib = (unsigned)d;
                unsigned ballot = __ballot_sync(0xFFFFFFFFu, flag == 2u);
                if (ballot) {
                    int L = __ffs(ballot) - 1;
                    if (lane > L) contrib = 0u;
                    ex += __reduce_add_sync(0xFFFFFFFFu, contrib);
                    break;
                } else {
                    ex += __reduce_add_sync(0xFFFFFFFFu, contrib);
                    base -= 32;
                }
            }
            if (lane == 0) {
                atomicExch(&g_desc[b],
                    ((unsigned long long)2u << 32) | (unsigned long long)(ex + blocksum));
                s_prefix = ex;
            }
        }
    }
    __syncthreads();
    g_hist[b * SCAN_BLOCK + t] = s_prefix + warp_off + inc - v;  // exclusive
}

// ---------------- scatter (4 points / thread) ----------------
__device__ __forceinline__ void scatter_one(float x, float y, float z, int idx) {
    unsigned key = morton3(x, y, z);
    unsigned pos = atomicAdd(&g_hist[key], 1u);
    g_pts[pos] = make_float4(x, y, z, __int_as_float(idx));
}

__global__ void k_scatter(const float* __restrict__ coords, int n) {
    int i = blockIdx.x * blockDim.x + threadIdx.x;
    int p0 = i * 4;
    if (p0 + 3 < n) {
        const float4* c4 = (const float4*)coords;
        float4 a = __ldg(&c4[i * 3 + 0]);
        float4 b = __ldg(&c4[i * 3 + 1]);
        float4 c = __ldg(&c4[i * 3 + 2]);
        scatter_one(a.x, a.y, a.z, p0 + 0);
        scatter_one(a.w, b.x, b.y, p0 + 1);
        scatter_one(b.z, b.w, c.x, p0 + 2);
        scatter_one(c.y, c.z, c.w, p0 + 3);
    } else {
        for (int p = p0; p < n; ++p)
            scatter_one(coords[3*p], coords[3*p+1], coords[3*p+2], p);
    }
}

// pick element idx (0..63) from the 64-wide per-warp register array {v0,v1}
__device__ __forceinline__ float sel64(float v0, float v1, int idx) {
    float a = __shfl_sync(0xFFFFFFFFu, v0, idx & 31);
    float b = __shfl_sync(0xFFFFFFFFu, v1, idx & 31);
    return (idx < 32) ? a : b;
}

// ---------------- main kernel ----------------
// block = 512 threads = 16 warps; warp w handles level w for 32 sorted points.
__global__ __launch_bounds__(512)
void hashgrid_main(const float* __restrict__ tables,
                   float* __restrict__ out,
                   ResParams rp, int n_points)
{
    __shared__ float s_pt[32 * 4];      // x,y,z,permbits per point
    __shared__ float s_out[32][33];

    int t = threadIdx.x;
    int w = t >> 5;          // level
    int lane = t & 31;       // point within tile
    int base = blockIdx.x * 32;

    // cooperative coalesced load of 32 float4 (512B)
    if (t < 128) {
        int idx = base * 4 + t;
        s_pt[t] = (idx < n_points * 4) ? ((const float*)g_pts)[idx] : 0.0f;
    }
    __syncthreads();

    // All lanes compute (tail lanes use zero coords; stores guarded below).
    float cx = s_pt[lane * 4 + 0];
    float cy = s_pt[lane * 4 + 1];
    float cz = s_pt[lane * 4 + 2];

    int ires = rp.r[w];
    float res = (float)ires;

    float sx = cx * res, sy = cy * res, sz = cz * res;
    float fx = floorf(sx), fy = floorf(sy), fz = floorf(sz);
    float wx = sx - fx, wy = sy - fy, wz = sz - fz;

    int ifx = (int)fx, ify = (int)fy, ifz = (int)fz;

    const float2* __restrict__ tbl =
        (const float2*)tables + (size_t)w * TABLE_SIZE;

    float2 f000, f001, f010, f011, f100, f101, f110, f111;

    // warp-uniform corner-lattice bounding brick (hardware REDUX)
    int mnx = __reduce_min_sync(0xFFFFFFFFu, ifx);
    int mny = __reduce_min_sync(0xFFFFFFFFu, ify);
    int mnz = __reduce_min_sync(0xFFFFFFFFu, ifz);
    int bx = __reduce_max_sync(0xFFFFFFFFu, ifx) - mnx + 2;
    int by = __reduce_max_sync(0xFFFFFFFFu, ify) - mny + 2;
    int bz = __reduce_max_sync(0xFFFFFFFFu, ifz) - mnz + 2;
    int byz = by * bz;
    int nc = bx * byz;

    if (nc <= 64) {
        // register-resident brick: lane holds corners (lane) and (lane+32)
        float v0x, v0y, v1x, v1y;
        {
            int c = lane;
            int i = c / byz, rem = c - i * byz;
            int j = rem / bz, k = rem - j * bz;
            unsigned h = ((unsigned)((mnx + i) * ires)
                        + (unsigned)((mny + j) * ires) * P1
                        + (unsigned)((mnz + k) * ires) * P2) & HMASK;
            // clamp unused lanes to a valid index (value never selected)
            float2 v = __ldg(tbl + ((c < nc) ? h : 0u));
            v0x = v.x; v0y = v.y;
        }
        {
            int c = lane + 32;
            int i = c / byz, rem = c - i * byz;
            int j = rem / bz, k = rem - j * bz;
            unsigned h = ((unsigned)((mnx + i) * ires)
                        + (unsigned)((mny + j) * ires) * P1
                        + (unsigned)((mnz + k) * ires) * P2) & HMASK;
            float2 v = (nc > 32) ? __ldg(tbl + ((c < nc) ? h : 0u))
                                 : make_float2(0.f, 0.f);
            v1x = v.x; v1y = v.y;
        }
        int b000 = (ifx - mnx) * byz + (ify - mny) * bz + (ifz - mnz);
        int i001 = b000 + 1;
        int i010 = b000 + bz;
        int i011 = b000 + bz + 1;
        int i100 = b000 + byz;
        int i101 = b000 + byz + 1;
        int i110 = b000 + byz + bz;
        int i111 = b000 + byz + bz + 1;
        f000 = make_float2(sel64(v0x, v1x, b000), sel64(v0y, v1y, b000));
        f001 = make_float2(sel64(v0x, v1x, i001), sel64(v0y, v1y, i001));
        f010 = make_float2(sel64(v0x, v1x, i010), sel64(v0y, v1y, i010));
        f011 = make_float2(sel64(v0x, v1x, i011), sel64(v0y, v1y, i011));
        f100 = make_float2(sel64(v0x, v1x, i100), sel64(v0y, v1y, i100));
        f101 = make_float2(sel64(v0x, v1x, i101), sel64(v0y, v1y, i101));
        f110 = make_float2(sel64(v0x, v1x, i110), sel64(v0y, v1y, i110));
        f111 = make_float2(sel64(v0x, v1x, i111), sel64(v0y, v1y, i111));
    } else {
        // per-lane gathers (fine levels): 8 independent LDG.64
        unsigned ux = (unsigned)(ifx * ires);
        unsigned uy = (unsigned)(ify * ires) * P1;
        unsigned uz = (unsigned)(ifz * ires) * P2;
        unsigned dx = (unsigned)ires;
        unsigned dy = (unsigned)ires * P1;
        unsigned dz = (unsigned)ires * P2;

        f000 = __ldg(tbl + ((ux      + uy      + uz     ) & HMASK));
        f001 = __ldg(tbl + ((ux      + uy      + uz + dz) & HMASK));
        f010 = __ldg(tbl + ((ux      + uy + dy + uz     ) & HMASK));
        f011 = __ldg(tbl + ((ux      + uy + dy + uz + dz) & HMASK));
        f100 = __ldg(tbl + ((ux + dx + uy      + uz     ) & HMASK));
        f101 = __ldg(tbl + ((ux + dx + uy      + uz + dz) & HMASK));
        f110 = __ldg(tbl + ((ux + dx + uy + dy + uz     ) & HMASK));
        f111 = __ldg(tbl + ((ux + dx + uy + dy + uz + dz) & HMASK));
    }

    float ex = 1.0f - wx, ey = 1.0f - wy, ez = 1.0f - wz;

    float c00a = f000.x * ex + f100.x * wx;
    float c00b = f000.y * ex + f100.y * wx;
    float c01a = f001.x * ex + f101.x * wx;
    float c01b = f001.y * ex + f101.y * wx;
    float c10a = f010.x * ex + f110.x * wx;
    float c10b = f010.y * ex + f110.y * wx;
    float c11a = f011.x * ex + f111.x * wx;
    float c11b = f011.y * ex + f111.y * wx;

    float c0a = c00a * ey + c10a * wy;
    float c0b = c00b * ey + c10b * wy;
    float c1a = c01a * ey + c11a * wy;
    float c1b = c01b * ey + c11b * wy;

    s_out[lane][2 * w]     = c0a * ez + c1a * wz;
    s_out[lane][2 * w + 1] = c0b * ez + c1b * wz;
    __syncthreads();

    // coalesced writeout: warp w writes rows w and w+16 (128B contiguous each)
    #pragma unroll
    for (int it = 0; it < 2; ++it) {
        int row = w + 16 * it;
        if (base + row < n_points) {
            int gp = __float_as_int(s_pt[row * 4 + 3]);
            out[(size_t)gp * 32 + lane] = s_out[row][lane];
        }
    }
}

// ---------------- launch ----------------
extern "C" void kernel_launch(void* const* d_in, const int* in_sizes, int n_in,
                              void* d_out, int out_size)
{
    const float* coords = (const float*)d_in[0];
    const float* tables = (const float*)d_in[1];
    float* out = (float*)d_out;
    int n_points = in_sizes[0] / 3;

    ResParams rp;
    double g = std::log(512.0 / 16.0) / 15.0;
    for (int l = 0; l < NLV; ++l)
        rp.r[l] = (int)std::floor(16.0 * std::exp((double)l * g));

    void* hist_ptr = nullptr;
    cudaGetSymbolAddress(&hist_ptr, g_hist);
    cudaMemsetAsync(hist_ptr, 0, NBINS * sizeof(unsigned));
    void* desc_ptr = nullptr;
    cudaGetSymbolAddress(&desc_ptr, g_desc);
    cudaMemsetAsync(desc_ptr, 0, NSCAN_BLOCKS * sizeof(unsigned long long));

    int b = 256;
    int ngroups = (n_points + 4 * b - 1) / (4 * b);
    k_hist<<<ngroups, b>>>(coords, n_points);
    k_scan_lookback<<<NSCAN_BLOCKS, SCAN_BLOCK>>>();
    k_scatter<<<ngroups, b>>>(coords, n_points);

    int ntiles = (n_points + 31) / 32;
    hashgrid_main<<<ntiles, 512>>>(tables, out, rp, n_points);
}

// round 9
// speedup vs baseline: 1.4149x; 1.0810x over previous
#include <cuda_runtime.h>
#include <cmath>

#define NLV 16
#define TABLE_SIZE (1u << 19)
#define HMASK (TABLE_SIZE - 1u)
#define P1 2654435761u
#define P2 805459861u

#define NP_MAX 1000000
#define GRID_BITS 6
#define GRID_RES (1 << GRID_BITS)          // 64
#define NBINS (1 << (3 * GRID_BITS))       // 262144
#define SCAN_BLOCK 512
#define NSCAN_BLOCKS (NBINS / SCAN_BLOCK)  // 512

struct ResParams { int r[NLV]; };

// ---- scratch (static device globals; no allocation) ----
__device__ unsigned g_hist[NBINS];
__device__ unsigned g_blocksums[NSCAN_BLOCKS];
__device__ float4   g_pts[NP_MAX];   // x,y,z, perm-as-bits

// ---------------- Morton ----------------
__device__ __forceinline__ unsigned expand_bits(unsigned v) {
    v &= 0x3FFu;
    v = (v | (v << 16)) & 0x030000FFu;
    v = (v | (v << 8))  & 0x0300F00Fu;
    v = (v | (v << 4))  & 0x030C30C3u;
    v = (v | (v << 2))  & 0x09249249u;
    return v;
}
__device__ __forceinline__ unsigned morton3(float x, float y, float z) {
    unsigned ix = min((unsigned)(x * (float)GRID_RES), (unsigned)(GRID_RES - 1));
    unsigned iy = min((unsigned)(y * (float)GRID_RES), (unsigned)(GRID_RES - 1));
    unsigned iz = min((unsigned)(z * (float)GRID_RES), (unsigned)(GRID_RES - 1));
    return (expand_bits(ix) << 2) | (expand_bits(iy) << 1) | expand_bits(iz);
}

// ---------------- hist ----------------
__global__ void k_hist(const float* __restrict__ coords, int n) {
    int i = blockIdx.x * blockDim.x + threadIdx.x;
    if (i >= n) return;
    unsigned key = morton3(coords[3 * i], coords[3 * i + 1], coords[3 * i + 2]);
    atomicAdd(&g_hist[key], 1u);
}

// ---------------- shfl block scans ----------------
__device__ __forceinline__ unsigned warp_incl_scan(unsigned v, int lane) {
    #pragma unroll
    for (int o = 1; o < 32; o <<= 1) {
        unsigned u = __shfl_up_sync(0xFFFFFFFFu, v, o);
        if (lane >= o) v += u;
    }
    return v;
}

// per-block exclusive scan of g_hist; blocksum to g_blocksums
__global__ __launch_bounds__(SCAN_BLOCK)
void k_scan1() {
    __shared__ unsigned warp_sums[16];
    int t = threadIdx.x;
    int lane = t & 31, w = t >> 5;
    int gi = blockIdx.x * SCAN_BLOCK + t;

    unsigned v = g_hist[gi];
    unsigned inc = warp_incl_scan(v, lane);
    if (lane == 31) warp_sums[w] = inc;
    __syncthreads();
    if (w == 0) {
        unsigned ws = (lane < 16) ? warp_sums[lane] : 0u;
        ws = warp_incl_scan(ws, lane);
        if (lane < 16) warp_sums[lane] = ws;
    }
    __syncthreads();
    unsigned warp_off = (w > 0) ? warp_sums[w - 1] : 0u;
    g_hist[gi] = warp_off + inc - v;            // block-local exclusive
    if (t == SCAN_BLOCK - 1) g_blocksums[blockIdx.x] = warp_off + inc;
}

// exclusive scan of the 512 block sums (one block)
__global__ __launch_bounds__(NSCAN_BLOCKS)
void k_scan2() {
    __shared__ unsigned warp_sums[16];
    int t = threadIdx.x;
    int lane = t & 31, w = t >> 5;
    unsigned v = g_blocksums[t];
    unsigned inc = warp_incl_scan(v, lane);
    if (lane == 31) warp_sums[w] = inc;
    __syncthreads();
    if (w == 0) {
        unsigned ws = (lane < 16) ? warp_sums[lane] : 0u;
        ws = warp_incl_scan(ws, lane);
        if (lane < 16) warp_sums[lane] = ws;
    }
    __syncthreads();
    unsigned warp_off = (w > 0) ? warp_sums[w - 1] : 0u;
    g_blocksums[t] = warp_off + inc - v;        // exclusive
}

// ---------------- scatter (adds blocksum inline; no scan3 kernel) ----------------
__global__ void k_scatter(const float* __restrict__ coords, int n) {
    int i = blockIdx.x * blockDim.x + threadIdx.x;
    if (i >= n) return;
    float x = coords[3 * i], y = coords[3 * i + 1], z = coords[3 * i + 2];
    unsigned key = morton3(x, y, z);
    unsigned pos = atomicAdd(&g_hist[key], 1u) + __ldg(&g_blocksums[key >> 9]);
    g_pts[pos] = make_float4(x, y, z, __int_as_float(i));  // one STG.128
}

// ---------------- main kernel ----------------
// block = 512 threads = 16 warps; warp w handles level w for 32 sorted points.
__global__ __launch_bounds__(512)
void hashgrid_main(const float* __restrict__ tables,
                   float* __restrict__ out,
                   ResParams rp, int n_points)
{
    __shared__ float s_pt[32 * 4];      // x,y,z,permbits per point
    __shared__ float s_out[32][33];

    int t = threadIdx.x;
    int w = t >> 5;          // level
    int lane = t & 31;       // point within tile
    int base = blockIdx.x * 32;

    // cooperative coalesced load of 32 float4 (512B)
    if (t < 128) {
        int idx = base * 4 + t;
        s_pt[t] = (idx < n_points * 4) ? ((const float*)g_pts)[idx] : 0.0f;
    }
    __syncthreads();

    int pi = base + lane;
    if (pi < n_points) {
        float cx = s_pt[lane * 4 + 0];
        float cy = s_pt[lane * 4 + 1];
        float cz = s_pt[lane * 4 + 2];

        int ires = rp.r[w];
        float res = (float)ires;

        float sx = cx * res, sy = cy * res, sz = cz * res;
        float fx = floorf(sx), fy = floorf(sy), fz = floorf(sz);
        float wx = sx - fx, wy = sy - fy, wz = sz - fz;

        // exact integer corner math; mod 2^19 via uint32 wrap
        unsigned ux = (unsigned)((int)fx * ires);
        unsigned uy = (unsigned)((int)fy * ires) * P1;
        unsigned uz = (unsigned)((int)fz * ires) * P2;
        unsigned dx = (unsigned)ires;
        unsigned dy = (unsigned)ires * P1;
        unsigned dz = (unsigned)ires * P2;

        const float2* __restrict__ tbl =
            (const float2*)tables + (size_t)w * TABLE_SIZE;

        float2 f000 = __ldg(tbl + ((ux      + uy      + uz     ) & HMASK));
        float2 f001 = __ldg(tbl + ((ux      + uy      + uz + dz) & HMASK));
        float2 f010 = __ldg(tbl + ((ux      + uy + dy + uz     ) & HMASK));
        float2 f011 = __ldg(tbl + ((ux      + uy + dy + uz + dz) & HMASK));
        float2 f100 = __ldg(tbl + ((ux + dx + uy      + uz     ) & HMASK));
        float2 f101 = __ldg(tbl + ((ux + dx + uy      + uz + dz) & HMASK));
        float2 f110 = __ldg(tbl + ((ux + dx + uy + dy + uz     ) & HMASK));
        float2 f111 = __ldg(tbl + ((ux + dx + uy + dy + uz + dz) & HMASK));

        float ex = 1.0f - wx, ey = 1.0f - wy, ez = 1.0f - wz;

        float c00a = f000.x * ex + f100.x * wx;
        float c00b = f000.y * ex + f100.y * wx;
        float c01a = f001.x * ex + f101.x * wx;
        float c01b = f001.y * ex + f101.y * wx;
        float c10a = f010.x * ex + f110.x * wx;
        float c10b = f010.y * ex + f110.y * wx;
        float c11a = f011.x * ex + f111.x * wx;
        float c11b = f011.y * ex + f111.y * wx;

        float c0a = c00a * ey + c10a * wy;
        float c0b = c00b * ey + c10b * wy;
        float c1a = c01a * ey + c11a * wy;
        float c1b = c01b * ey + c11b * wy;

        s_out[lane][2 * w]     = c0a * ez + c1a * wz;
        s_out[lane][2 * w + 1] = c0b * ez + c1b * wz;
    }
    __syncthreads();

    // coalesced writeout: warp w writes rows w and w+16 (128B contiguous each)
    #pragma unroll
    for (int it = 0; it < 2; ++it) {
        int row = w + 16 * it;
        if (base + row < n_points) {
            int gp = __float_as_int(s_pt[row * 4 + 3]);
            out[(size_t)gp * 32 + lane] = s_out[row][lane];
        }
    }
}

// ---------------- launch ----------------
extern "C" void kernel_launch(void* const* d_in, const int* in_sizes, int n_in,
                              void* d_out, int out_size)
{
    const float* coords = (const float*)d_in[0];
    const float* tables = (const float*)d_in[1];
    float* out = (float*)d_out;
    int n_points = in_sizes[0] / 3;

    ResParams rp;
    double g = std::log(512.0 / 16.0) / 15.0;
    for (int l = 0; l < NLV; ++l)
        rp.r[l] = (int)std::floor(16.0 * std::exp((double)l * g));

    void* hist_ptr = nullptr;
    cudaGetSymbolAddress(&hist_ptr, g_hist);
    cudaMemsetAsync(hist_ptr, 0, NBINS * sizeof(unsigned));

    int b = 256;
    int gpts = (n_points + b - 1) / b;
    k_hist<<<gpts, b>>>(coords, n_points);
    k_scan1<<<NSCAN_BLOCKS, SCAN_BLOCK>>>();
    k_scan2<<<1, NSCAN_BLOCKS>>>();
    k_scatter<<<gpts, b>>>(coords, n_points);

    int ntiles = (n_points + 31) / 32;
    hashgrid_main<<<ntiles, 512>>>(tables, out, rp, n_points);
}

// round 10
// speedup vs baseline: 1.5956x; 1.1278x over previous
#include <cuda_runtime.h>
#include <cmath>

#define NLV 16
#define TABLE_SIZE (1u << 19)
#define HMASK (TABLE_SIZE - 1u)
#define P1 2654435761u
#define P2 805459861u

#define NP_MAX 1000000
#define GRID_BITS 6
#define GRID_RES (1 << GRID_BITS)          // 64
#define NBINS (1 << (3 * GRID_BITS))       // 262144
#define SCAN_BLOCK 512
#define NSCAN_BLOCKS (NBINS / SCAN_BLOCK)  // 512

struct ResParams { int r[NLV]; };

// ---- scratch (static device globals; no allocation) ----
__device__ unsigned g_hist[NBINS];
__device__ unsigned g_blocksums[NSCAN_BLOCKS];
__device__ float4   g_pts[NP_MAX];   // x,y,z, perm-as-bits

// ---------------- Morton ----------------
__device__ __forceinline__ unsigned expand_bits(unsigned v) {
    v &= 0x3FFu;
    v = (v | (v << 16)) & 0x030000FFu;
    v = (v | (v << 8))  & 0x0300F00Fu;
    v = (v | (v << 4))  & 0x030C30C3u;
    v = (v | (v << 2))  & 0x09249249u;
    return v;
}
__device__ __forceinline__ unsigned morton3(float x, float y, float z) {
    unsigned ix = min((unsigned)(x * (float)GRID_RES), (unsigned)(GRID_RES - 1));
    unsigned iy = min((unsigned)(y * (float)GRID_RES), (unsigned)(GRID_RES - 1));
    unsigned iz = min((unsigned)(z * (float)GRID_RES), (unsigned)(GRID_RES - 1));
    return (expand_bits(ix) << 2) | (expand_bits(iy) << 1) | expand_bits(iz);
}

// ---------------- hist ----------------
__global__ void k_hist(const float* __restrict__ coords, int n) {
    int i = blockIdx.x * blockDim.x + threadIdx.x;
    if (i >= n) return;
    unsigned key = morton3(coords[3 * i], coords[3 * i + 1], coords[3 * i + 2]);
    atomicAdd(&g_hist[key], 1u);
}

// ---------------- shfl block scans ----------------
__device__ __forceinline__ unsigned warp_incl_scan(unsigned v, int lane) {
    #pragma unroll
    for (int o = 1; o < 32; o <<= 1) {
        unsigned u = __shfl_up_sync(0xFFFFFFFFu, v, o);
        if (lane >= o) v += u;
    }
    return v;
}

// per-block exclusive scan of g_hist; blocksum to g_blocksums
__global__ __launch_bounds__(SCAN_BLOCK)
void k_scan1() {
    __shared__ unsigned warp_sums[16];
    int t = threadIdx.x;
    int lane = t & 31, w = t >> 5;
    int gi = blockIdx.x * SCAN_BLOCK + t;

    unsigned v = g_hist[gi];
    unsigned inc = warp_incl_scan(v, lane);
    if (lane == 31) warp_sums[w] = inc;
    __syncthreads();
    if (w == 0) {
        unsigned ws = (lane < 16) ? warp_sums[lane] : 0u;
        ws = warp_incl_scan(ws, lane);
        if (lane < 16) warp_sums[lane] = ws;
    }
    __syncthreads();
    unsigned warp_off = (w > 0) ? warp_sums[w - 1] : 0u;
    g_hist[gi] = warp_off + inc - v;            // block-local exclusive
    if (t == SCAN_BLOCK - 1) g_blocksums[blockIdx.x] = warp_off + inc;
}

// exclusive scan of the 512 block sums (one block)
__global__ __launch_bounds__(NSCAN_BLOCKS)
void k_scan2() {
    __shared__ unsigned warp_sums[16];
    int t = threadIdx.x;
    int lane = t & 31, w = t >> 5;
    unsigned v = g_blocksums[t];
    unsigned inc = warp_incl_scan(v, lane);
    if (lane == 31) warp_sums[w] = inc;
    __syncthreads();
    if (w == 0) {
        unsigned ws = (lane < 16) ? warp_sums[lane] : 0u;
        ws = warp_incl_scan(ws, lane);
        if (lane < 16) warp_sums[lane] = ws;
    }
    __syncthreads();
    unsigned warp_off = (w > 0) ? warp_sums[w - 1] : 0u;
    g_blocksums[t] = warp_off + inc - v;        // exclusive
}

// ---------------- scatter (adds blocksum inline; no scan3 kernel) ----------------
__global__ void k_scatter(const float* __restrict__ coords, int n) {
    int i = blockIdx.x * blockDim.x + threadIdx.x;
    if (i >= n) return;
    float x = coords[3 * i], y = coords[3 * i + 1], z = coords[3 * i + 2];
    unsigned key = morton3(x, y, z);
    unsigned pos = atomicAdd(&g_hist[key], 1u) + __ldg(&g_blocksums[key >> 9]);
    g_pts[pos] = make_float4(x, y, z, __int_as_float(i));  // one STG.128
}

// ---------------- main kernel ----------------
// block = 256 threads = 8 warps, 32 points/tile.
// Warp w processes level w (coarse, L1-resident) AND level 15-w (fine,
// L2-latency) — pairing balances per-warp latency so no warp idles at the
// barrier, and the x2 unroll gives up to 16 outstanding gathers per warp.
__global__ __launch_bounds__(256)
void hashgrid_main(const float* __restrict__ tables,
                   float* __restrict__ out,
                   ResParams rp, int n_points)
{
    __shared__ float s_pt[32 * 4];      // x,y,z,permbits per point
    __shared__ float s_out[32][33];

    int t = threadIdx.x;
    int w = t >> 5;          // warp 0..7
    int lane = t & 31;       // point within tile
    int base = blockIdx.x * 32;

    // cooperative coalesced load of 32 float4 (512B)
    if (t < 128) {
        int idx = base * 4 + t;
        s_pt[t] = (idx < n_points * 4) ? ((const float*)g_pts)[idx] : 0.0f;
    }
    __syncthreads();

    int pi = base + lane;
    if (pi < n_points) {
        float cx = s_pt[lane * 4 + 0];
        float cy = s_pt[lane * 4 + 1];
        float cz = s_pt[lane * 4 + 2];

        #pragma unroll
        for (int it = 0; it < 2; ++it) {
            int l = (it == 0) ? w : (NLV - 1 - w);
            int ires = rp.r[l];
            float res = (float)ires;

            float sx = cx * res, sy = cy * res, sz = cz * res;
            float fx = floorf(sx), fy = floorf(sy), fz = floorf(sz);
            float wx = sx - fx, wy = sy - fy, wz = sz - fz;

            // exact integer corner math; mod 2^19 via uint32 wrap
            unsigned ux = (unsigned)((int)fx * ires);
            unsigned uy = (unsigned)((int)fy * ires) * P1;
            unsigned uz = (unsigned)((int)fz * ires) * P2;
            unsigned dx = (unsigned)ires;
            unsigned dy = (unsigned)ires * P1;
            unsigned dz = (unsigned)ires * P2;

            const float2* __restrict__ tbl =
                (const float2*)tables + (size_t)l * TABLE_SIZE;

            float2 f000 = __ldg(tbl + ((ux      + uy      + uz     ) & HMASK));
            float2 f001 = __ldg(tbl + ((ux      + uy      + uz + dz) & HMASK));
            float2 f010 = __ldg(tbl + ((ux      + uy + dy + uz     ) & HMASK));
            float2 f011 = __ldg(tbl + ((ux      + uy + dy + uz + dz) & HMASK));
            float2 f100 = __ldg(tbl + ((ux + dx + uy      + uz     ) & HMASK));
            float2 f101 = __ldg(tbl + ((ux + dx + uy      + uz + dz) & HMASK));
            float2 f110 = __ldg(tbl + ((ux + dx + uy + dy + uz     ) & HMASK));
            float2 f111 = __ldg(tbl + ((ux + dx + uy + dy + uz + dz) & HMASK));

            float ex = 1.0f - wx, ey = 1.0f - wy, ez = 1.0f - wz;

            float c00a = f000.x * ex + f100.x * wx;
            float c00b = f000.y * ex + f100.y * wx;
            float c01a = f001.x * ex + f101.x * wx;
            float c01b = f001.y * ex + f101.y * wx;
            float c10a = f010.x * ex + f110.x * wx;
            float c10b = f010.y * ex + f110.y * wx;
            float c11a = f011.x * ex + f111.x * wx;
            float c11b = f011.y * ex + f111.y * wx;

            float c0a = c00a * ey + c10a * wy;
            float c0b = c00b * ey + c10b * wy;
            float c1a = c01a * ey + c11a * wy;
            float c1b = c01b * ey + c11b * wy;

            s_out[lane][2 * l]     = c0a * ez + c1a * wz;
            s_out[lane][2 * l + 1] = c0b * ez + c1b * wz;
        }
    }
    __syncthreads();

    // coalesced writeout: warp w writes rows 4w..4w+3 (128B contiguous each)
    #pragma unroll
    for (int it = 0; it < 4; ++it) {
        int row = w * 4 + it;
        if (base + row < n_points) {
            int gp = __float_as_int(s_pt[row * 4 + 3]);
            out[(size_t)gp * 32 + lane] = s_out[row][lane];
        }
    }
}

// ---------------- launch ----------------
extern "C" void kernel_launch(void* const* d_in, const int* in_sizes, int n_in,
                              void* d_out, int out_size)
{
    const float* coords = (const float*)d_in[0];
    const float* tables = (const float*)d_in[1];
    float* out = (float*)d_out;
    int n_points = in_sizes[0] / 3;

    ResParams rp;
    double g = std::log(512.0 / 16.0) / 15.0;
    for (int l = 0; l < NLV; ++l)
        rp.r[l] = (int)std::floor(16.0 * std::exp((double)l * g));

    void* hist_ptr = nullptr;
    cudaGetSymbolAddress(&hist_ptr, g_hist);
    cudaMemsetAsync(hist_ptr, 0, NBINS * sizeof(unsigned));

    int b = 256;
    int gpts = (n_points + b - 1) / b;
    k_hist<<<gpts, b>>>(coords, n_points);
    k_scan1<<<NSCAN_BLOCKS, SCAN_BLOCK>>>();
    k_scan2<<<1, NSCAN_BLOCKS>>>();
    k_scatter<<<gpts, b>>>(coords, n_points);

    int ntiles = (n_points + 31) / 32;
    hashgrid_main<<<ntiles, 256>>>(tables, out, rp, n_points);
}